// round 1
// baseline (speedup 1.0000x reference)
#include <cuda_runtime.h>
#include <cuda_bf16.h>
#include <math.h>

#define L 4096
#define E 300
#define H 512
#define G 2048   // 4*H
#define TT 24
#define XW 1024  // 2*H

#define RB 64      // blocks per LSTM direction
#define RTH 256    // threads per LSTM block

// ------------------------ scratch (no allocs allowed) ------------------------
__device__ float g_pre0f[(size_t)L * G];
__device__ float g_pre0b[(size_t)L * G];
__device__ float g_pre1f[(size_t)L * G];
__device__ float g_pre1b[(size_t)L * G];
__device__ float g_x1[(size_t)L * XW];
__device__ float g_x2[(size_t)L * XW];
__device__ float g_emis[(size_t)L * TT];
__device__ float g_h[2 * H];          // current h per direction (stale-safe: step 0 never reads it)
__device__ int   g_bar[2 * 2 * L];    // [layer][dir][step] arrival counters

// ------------------------ helpers ------------------------
__device__ __forceinline__ float warp_sum(float v) {
#pragma unroll
    for (int o = 16; o > 0; o >>= 1) v += __shfl_down_sync(0xffffffffu, v, o);
    return v;
}
__device__ __forceinline__ float warp_max_all(float v) {
#pragma unroll
    for (int o = 16; o > 0; o >>= 1) v = fmaxf(v, __shfl_xor_sync(0xffffffffu, v, o));
    return v;
}
__device__ __forceinline__ float sigmoidf_(float x) { return 1.0f / (1.0f + __expf(-x)); }

// ------------------------ GEMM: C[M,N] = A[M,K] @ B[N,K]^T + bias[N] ------------------------
// BM=BN=128, BK=8, 256 threads, 8x8 microtile. Optional row gather on A (embedding lookup).
__global__ __launch_bounds__(256) void gemm_bias_kernel(
    const float* __restrict__ A, const int* __restrict__ rowmap,
    const float* __restrict__ B, const float* __restrict__ bias,
    float* __restrict__ C, int M, int N, int K)
{
    __shared__ float As[8][128];
    __shared__ float Bs[8][128];

    int tid = threadIdx.x;
    int bm = blockIdx.y, bn = blockIdx.x;
    int tx = tid & 15, ty = tid >> 4;

    int loadRow = tid >> 1;            // 0..127
    int loadCol = (tid & 1) * 4;       // 0 or 4

    int aRowG = bm * 128 + loadRow;
    int aPhys = rowmap ? rowmap[aRowG] : aRowG;
    const float* Aptr = A + (size_t)aPhys * K;
    const float* Bptr = B + (size_t)(bn * 128 + loadRow) * K;

    float acc[8][8];
#pragma unroll
    for (int i = 0; i < 8; i++)
#pragma unroll
        for (int j = 0; j < 8; j++) acc[i][j] = 0.0f;

    for (int k0 = 0; k0 < K; k0 += 8) {
        int k = k0 + loadCol;
        if (k + 3 < K) {
            float4 va = *(const float4*)(Aptr + k);
            As[loadCol + 0][loadRow] = va.x;
            As[loadCol + 1][loadRow] = va.y;
            As[loadCol + 2][loadRow] = va.z;
            As[loadCol + 3][loadRow] = va.w;
            float4 vb = *(const float4*)(Bptr + k);
            Bs[loadCol + 0][loadRow] = vb.x;
            Bs[loadCol + 1][loadRow] = vb.y;
            Bs[loadCol + 2][loadRow] = vb.z;
            Bs[loadCol + 3][loadRow] = vb.w;
        } else {
#pragma unroll
            for (int i = 0; i < 4; i++) {
                int kk = k + i;
                As[loadCol + i][loadRow] = (kk < K) ? Aptr[kk] : 0.0f;
                Bs[loadCol + i][loadRow] = (kk < K) ? Bptr[kk] : 0.0f;
            }
        }
        __syncthreads();
#pragma unroll
        for (int kk = 0; kk < 8; kk++) {
            float a[8], b[8];
#pragma unroll
            for (int i = 0; i < 8; i++) a[i] = As[kk][ty * 8 + i];
#pragma unroll
            for (int j = 0; j < 8; j++) b[j] = Bs[kk][tx * 8 + j];
#pragma unroll
            for (int i = 0; i < 8; i++)
#pragma unroll
                for (int j = 0; j < 8; j++) acc[i][j] += a[i] * b[j];
        }
        __syncthreads();
    }

#pragma unroll
    for (int i = 0; i < 8; i++) {
        int row = bm * 128 + ty * 8 + i;
#pragma unroll
        for (int j = 0; j < 8; j++) {
            int col = bn * 128 + tx * 8 + j;
            C[(size_t)row * N + col] = acc[i][j] + bias[col];
        }
    }
}

// ------------------------ persistent bidirectional LSTM layer ------------------------
// Grid = 2*RB blocks: blocks [0,RB) forward, [RB,2RB) backward. Each block owns 8 hidden
// units (32 gate rows, 64KB of W_hh -> L1 resident). Per-step grid barrier (per direction)
// via atomic counters. h exchanged through L2 (ld/st .cg).
__global__ __launch_bounds__(RTH) void lstm_kernel(
    const float* __restrict__ pre_f, const float* __restrict__ pre_b,
    const float* __restrict__ whh_f, const float* __restrict__ whh_b,
    float* __restrict__ out, int* __restrict__ bar)
{
    int dir = (blockIdx.x >= RB) ? 1 : 0;
    int blk = blockIdx.x - dir * RB;
    const float* pre = dir ? pre_b : pre_f;
    const float* whh = dir ? whh_b : whh_f;
    float* hg = g_h + dir * H;
    int* ctr = bar + dir * L;
    int dir_off = dir * H;

    __shared__ float h_sh[H];
    __shared__ float gates[32];

    int tid = threadIdx.x, lane = tid & 31, w = tid >> 5;
    int u0 = blk * 8;
    float c_state = 0.0f;  // meaningful for tid < 8

    for (int s = 0; s < L; s++) {
        int t = dir ? (L - 1 - s) : s;

        if (tid < 128) {
            if (s == 0) {
                ((float4*)h_sh)[tid] = make_float4(0.f, 0.f, 0.f, 0.f);
            } else {
                ((float4*)h_sh)[tid] = __ldcg((const float4*)hg + tid);
            }
        }
        __syncthreads();

        // 32 gate rows per block: lr = g*8 + uu ; row = g*512 + u0 + uu
#pragma unroll
        for (int i = 0; i < 4; i++) {
            int lr = w * 4 + i;
            int row = (lr >> 3) * H + u0 + (lr & 7);
            const float4* wp = (const float4*)(whh + (size_t)row * H);
            const float4* hp = (const float4*)h_sh;
            float acc = 0.0f;
#pragma unroll
            for (int q = 0; q < 4; q++) {
                float4 a = wp[lane + q * 32];
                float4 b = hp[lane + q * 32];
                acc += a.x * b.x + a.y * b.y + a.z * b.z + a.w * b.w;
            }
            acc = warp_sum(acc);
            if (lane == 0) gates[lr] = acc + pre[(size_t)t * G + row];
        }
        __syncthreads();

        if (tid < 8) {
            float iv = sigmoidf_(gates[tid]);
            float fv = sigmoidf_(gates[8 + tid]);
            float gv = tanhf(gates[16 + tid]);
            float ov = sigmoidf_(gates[24 + tid]);
            c_state = fv * c_state + iv * gv;
            float hv = ov * tanhf(c_state);
            int u = u0 + tid;
            out[(size_t)t * XW + dir_off + u] = hv;
            __stcg(hg + u, hv);
            __threadfence();
        }
        __syncthreads();

        if (tid == 0) {
            __threadfence();
            int old = atomicAdd(ctr + s, 1);
            if (old < RB - 1) {
                int v;
                do {
                    asm volatile("ld.global.cg.s32 %0, [%1];" : "=r"(v) : "l"(ctr + s) : "memory");
                } while (v < RB);
            }
            __threadfence();
        }
        __syncthreads();
    }
}

// ------------------------ emissions: e[L,24] = x2 @ w_out^T + b_out ------------------------
__global__ __launch_bounds__(256) void emis_kernel(
    const float* __restrict__ w_out, const float* __restrict__ b_out)
{
    int tid = threadIdx.x, lane = tid & 31, w = tid >> 5;
    int t = blockIdx.x * 8 + w;
    const float4* xp = (const float4*)(g_x2 + (size_t)t * XW);
    float4 xr[8];
#pragma unroll
    for (int q = 0; q < 8; q++) xr[q] = xp[lane + q * 32];
    for (int j = 0; j < TT; j++) {
        const float4* wp = (const float4*)(w_out + (size_t)j * XW);
        float acc = 0.0f;
#pragma unroll
        for (int q = 0; q < 8; q++) {
            float4 wv = wp[lane + q * 32];
            acc += xr[q].x * wv.x + xr[q].y * wv.y + xr[q].z * wv.z + xr[q].w * wv.w;
        }
        acc = warp_sum(acc);
        if (lane == 0) g_emis[(size_t)t * TT + j] = acc + b_out[j];
    }
}

// ------------------------ CRF NLL ------------------------
__global__ __launch_bounds__(768) void crf_kernel(
    const float* __restrict__ start_trans, const float* __restrict__ end_trans,
    const float* __restrict__ trans, const int* __restrict__ tags,
    float* __restrict__ outp)
{
    __shared__ float trans_sh[TT * 25];
    __shared__ float alpha[2][TT];
    __shared__ float red[24];
    __shared__ float num_sh;

    int tid = threadIdx.x, lane = tid & 31, w = tid >> 5;

    // numerator (parallel part)
    float p = 0.0f;
    for (int t = tid; t < L; t += 768) p += g_emis[(size_t)t * TT + tags[t]];
    for (int t = tid; t < L - 1; t += 768) p += trans[tags[t] * TT + tags[t + 1]];
    p = warp_sum(p);
    if (lane == 0) red[w] = p;

    for (int i = tid; i < TT * TT; i += 768)
        trans_sh[(i / TT) * 25 + (i % TT)] = trans[i];
    if (tid < TT) alpha[0][tid] = start_trans[tid] + g_emis[tid];
    __syncthreads();

    if (w == 0) {
        float q = (lane < 24) ? red[lane] : 0.0f;
        q = warp_sum(q);
        if (lane == 0) num_sh = q + start_trans[tags[0]] + end_trans[tags[L - 1]];
    }
    __syncthreads();

    // forward scan: warp j computes alpha'[j] = logsumexp_i(alpha[i] + trans[i][j]) + e[t][j]
    for (int t = 1; t < L; t++) {
        int cur = t & 1, prv = cur ^ 1;
        if (w < TT) {
            float v = (lane < TT) ? alpha[prv][lane] + trans_sh[lane * 25 + w] : -1e30f;
            float m = warp_max_all(v);
            float e = (lane < TT) ? __expf(v - m) : 0.0f;
            float ssum = warp_sum(e);
            if (lane == 0) alpha[cur][w] = m + logf(ssum) + g_emis[(size_t)t * TT + w];
        }
        __syncthreads();
    }

    if (tid < 32) {
        int tl = (L - 1) & 1;
        float v = (lane < TT) ? alpha[tl][lane] + end_trans[lane] : -1e30f;
        float m = warp_max_all(v);
        float e = (lane < TT) ? __expf(v - m) : 0.0f;
        float ssum = warp_sum(e);
        if (lane == 0) outp[0] = (m + logf(ssum)) - num_sh;
    }
}

// ------------------------ launch ------------------------
extern "C" void kernel_launch(void* const* d_in, const int* in_sizes, int n_in,
                              void* d_out, int out_size)
{
    const float* emb       = (const float*)d_in[0];
    const float* w_ih_l0f  = (const float*)d_in[1];
    const float* w_hh_l0f  = (const float*)d_in[2];
    const float* b_l0f     = (const float*)d_in[3];
    const float* w_ih_l0b  = (const float*)d_in[4];
    const float* w_hh_l0b  = (const float*)d_in[5];
    const float* b_l0b     = (const float*)d_in[6];
    const float* w_ih_l1f  = (const float*)d_in[7];
    const float* w_hh_l1f  = (const float*)d_in[8];
    const float* b_l1f     = (const float*)d_in[9];
    const float* w_ih_l1b  = (const float*)d_in[10];
    const float* w_hh_l1b  = (const float*)d_in[11];
    const float* b_l1b     = (const float*)d_in[12];
    const float* w_out     = (const float*)d_in[13];
    const float* b_out     = (const float*)d_in[14];
    const float* start_tr  = (const float*)d_in[15];
    const float* end_tr    = (const float*)d_in[16];
    const float* trans     = (const float*)d_in[17];
    const int*   sentence  = (const int*)d_in[18];
    const int*   tags      = (const int*)d_in[19];
    float* outp = (float*)d_out;

    float *pre0f, *pre0b, *pre1f, *pre1b, *x1, *x2;
    int* bar;
    cudaGetSymbolAddress((void**)&pre0f, g_pre0f);
    cudaGetSymbolAddress((void**)&pre0b, g_pre0b);
    cudaGetSymbolAddress((void**)&pre1f, g_pre1f);
    cudaGetSymbolAddress((void**)&pre1b, g_pre1b);
    cudaGetSymbolAddress((void**)&x1, g_x1);
    cudaGetSymbolAddress((void**)&x2, g_x2);
    cudaGetSymbolAddress((void**)&bar, g_bar);

    cudaMemsetAsync(bar, 0, 2 * 2 * L * sizeof(int));

    dim3 ggrid(G / 128, L / 128);  // (16, 32)

    // layer 0 input pre-activations (with embedding gather)
    gemm_bias_kernel<<<ggrid, 256>>>(emb, sentence, w_ih_l0f, b_l0f, pre0f, L, G, E);
    gemm_bias_kernel<<<ggrid, 256>>>(emb, sentence, w_ih_l0b, b_l0b, pre0b, L, G, E);

    // layer 0 recurrence (both directions) -> x1 = concat(hf, hb)
    lstm_kernel<<<2 * RB, RTH>>>(pre0f, pre0b, w_hh_l0f, w_hh_l0b, x1, bar);

    // layer 1 input pre-activations
    gemm_bias_kernel<<<ggrid, 256>>>(x1, nullptr, w_ih_l1f, b_l1f, pre1f, L, G, XW);
    gemm_bias_kernel<<<ggrid, 256>>>(x1, nullptr, w_ih_l1b, b_l1b, pre1b, L, G, XW);

    // layer 1 recurrence -> x2
    lstm_kernel<<<2 * RB, RTH>>>(pre1f, pre1b, w_hh_l1f, w_hh_l1b, x2, bar + 2 * L);

    // emissions + CRF
    emis_kernel<<<L / 8, 256>>>(w_out, b_out);
    crf_kernel<<<1, 768>>>(start_tr, end_tr, trans, tags, outp);
}